// round 8
// baseline (speedup 1.0000x reference)
#include <cuda_runtime.h>
#include <cuda_bf16.h>

#define STEPS 16

// ---- coefficient tables (identical to R7, which passed) ------------------
// Warp slice c (0..3) owns elements [256c, 256c+256); lane L owns the 8
// elements e0..e7 = 256c + 8L + {0..7} of its 4 rows.
// Even pairs  p = 128c + 4L + j, j=0..3 : (e2j, e2j+1)           lane-internal
// Odd  pairs  q = 128c + 4L + j, j=0..2 : (e2j+1, e2j+2)         lane-internal
//             q = 128c + 4L + 3         : (e7, next-lane e0)     boundary
//             q = 128c + 4L - 1         : (left-lane e7, e0)     boundary
// A-tables: (cx, cy, cz, cw) = (sp*ct, cp*ct, sp*st, cp*st)  [a'-update]
// B-tables: packed (ct, st) per pair                          [b'-update]
//   gOB[s][c][1][L] = (ct_q2, st_q2, ct_left, st_left)
// Nonexistent pairs (q=-1, q=511) -> exact identity.
__device__ float4 gEA[STEPS][4][4][32];
__device__ float4 gEB[STEPS][4][2][32];
__device__ float4 gOA[STEPS][4][4][32];
__device__ float4 gOB[STEPS][4][2][32];
__device__ float2 g_om[1024];

__global__ void eunn_precompute(const float* __restrict__ omega,
                                const float* __restrict__ et,
                                const float* __restrict__ ot,
                                const float* __restrict__ ep,
                                const float* __restrict__ op)
{
    int idx = blockIdx.x * blockDim.x + threadIdx.x;
    if (idx < 8192) {
        int s = idx >> 9, p = idx & 511;
        int c = p >> 7, w = p & 127, L = w >> 2, j = w & 3;
        float st, ct, sp, cp;
        sincosf(et[s * 512 + p], &st, &ct);
        sincosf(ep[s * 512 + p], &sp, &cp);
        gEA[s][c][j][L] = make_float4(sp * ct, cp * ct, sp * st, cp * st);
        ((float2*)&gEB[s][c][j >> 1][L])[j & 1] = make_float2(ct, st);
    } else if (idx < 16384) {
        int t = idx - 8192;
        int s = t >> 9, q = t & 511;
        if (q < 511) {                       // NB: ot/op row stride is 511
            int c = q >> 7, w = q & 127, L = w >> 2, j = w & 3;
            float st, ct, sp, cp;
            sincosf(ot[s * 511 + q], &st, &ct);
            sincosf(op[s * 511 + q], &sp, &cp);
            gOA[s][c][j][L] = make_float4(sp * ct, cp * ct, sp * st, cp * st);
            if (j == 0)      ((float2*)&gOB[s][c][0][L])[0] = make_float2(ct, st);
            else if (j == 1) ((float2*)&gOB[s][c][0][L])[1] = make_float2(ct, st);
            else if (j == 2) ((float2*)&gOB[s][c][1][L])[0] = make_float2(ct, st);
            else {
                int q1 = q + 1;
                int cn = q1 >> 7, Ln = (q1 & 127) >> 2;
                ((float2*)&gOB[s][cn][1][Ln])[1] = make_float2(ct, st);
            }
        } else {
            gOA[s][3][3][31] = make_float4(1.f, 0.f, 0.f, 0.f);
            ((float2*)&gOB[s][0][1][0])[1] = make_float2(1.f, 0.f);
        }
    } else if (idx < 17408) {
        int h = idx - 16384;
        float sn, cs;
        sincosf(omega[h], &sn, &cs);
        g_om[h] = make_float2(cs, sn);
    }
}

// full 12-FMA rotation of pair (A, B)
#define ROT(Ar, Ai, Br, Bi, c4, dt, ds)                                    \
    do {                                                                   \
        float _ar = (Ar), _ai = (Ai), _br = (Br), _bi = (Bi);              \
        (Ar) = _ar * (c4).x - _ai * (c4).y - _br * (c4).z + _bi * (c4).w;  \
        (Ai) = _ar * (c4).y + _ai * (c4).x - _br * (c4).w - _bi * (c4).z;  \
        (Br) = _br * (dt) + _ar * (ds);                                    \
        (Bi) = _bi * (dt) + _ai * (ds);                                    \
    } while (0)

// Block = 256 threads = 2 row-groups (g) x 4 slice-warps (c).
// Warp (g,c), lane L: elements 256c + 8L + {0..7} of rows row0..row0+3.
// 3 CTAs/SM target: <=84 regs, so coefficients are loaded in 4 small
// sub-phases (max 3 float4 live) instead of one 12-float4 prefetch.
__global__ void __launch_bounds__(256, 3)
eunn_main(const float* __restrict__ x, float* __restrict__ out)
{
    __shared__ float sE0[2][2][4][4][2];   // [parity][g][slice][row][re/im]
    __shared__ float sE7[2][2][4][4][2];

    int lane  = threadIdx.x & 31;
    int wblk  = threadIdx.x >> 5;
    int c     = wblk & 3;
    int g     = wblk >> 2;
    int row0  = blockIdx.x * 8 + g * 4;
    int ebase = c * 256 + lane * 8;

    float xr[4][8], xi[4][8];
#pragma unroll
    for (int r = 0; r < 4; r++) {
        const float4* p4 = (const float4*)(x + (size_t)(row0 + r) * 2048 + ebase * 2);
#pragma unroll
        for (int i = 0; i < 4; i++) {
            float4 v = __ldg(&p4[i]);
            xr[r][2*i] = v.x; xi[r][2*i] = v.y; xr[r][2*i+1] = v.z; xi[r][2*i+1] = v.w;
        }
    }

#pragma unroll 1
    for (int s = 0; s < STEPS; s++) {
        int par = s & 1;

        // ---- even sub-phase A: pairs (e0,e1), (e2,e3) ----
        {
            float4 EA0 = gEA[s][c][0][lane];
            float4 EA1 = gEA[s][c][1][lane];
            float4 EB0 = gEB[s][c][0][lane];
#pragma unroll
            for (int r = 0; r < 4; r++) {
                ROT(xr[r][0], xi[r][0], xr[r][1], xi[r][1], EA0, EB0.x, EB0.y);
                ROT(xr[r][2], xi[r][2], xr[r][3], xi[r][3], EA1, EB0.z, EB0.w);
            }
        }
        // ---- even sub-phase B: pairs (e4,e5), (e6,e7) ----
        {
            float4 EA2 = gEA[s][c][2][lane];
            float4 EA3 = gEA[s][c][3][lane];
            float4 EB1 = gEB[s][c][1][lane];
#pragma unroll
            for (int r = 0; r < 4; r++) {
                ROT(xr[r][4], xi[r][4], xr[r][5], xi[r][5], EA2, EB1.x, EB1.y);
                ROT(xr[r][6], xi[r][6], xr[r][7], xi[r][7], EA3, EB1.z, EB1.w);
            }
        }

        // publish post-even slice edges
        if (lane == 0) {
#pragma unroll
            for (int r = 0; r < 4; r++) {
                sE0[par][g][c][r][0] = xr[r][0];
                sE0[par][g][c][r][1] = xi[r][0];
            }
        }
        if (lane == 31) {
#pragma unroll
            for (int r = 0; r < 4; r++) {
                sE7[par][g][c][r][0] = xr[r][7];
                sE7[par][g][c][r][1] = xi[r][7];
            }
        }
        asm volatile("bar.sync %0, 128;" :: "r"(g + 1) : "memory");

        // ---- odd sub-phase A: internal pairs (e1,e2), (e3,e4) ----
        {
            float4 OA0 = gOA[s][c][0][lane];
            float4 OA1 = gOA[s][c][1][lane];
            float4 OB0 = gOB[s][c][0][lane];
#pragma unroll
            for (int r = 0; r < 4; r++) {
                ROT(xr[r][1], xi[r][1], xr[r][2], xi[r][2], OA0, OB0.x, OB0.y);
                ROT(xr[r][3], xi[r][3], xr[r][4], xi[r][4], OA1, OB0.z, OB0.w);
            }
        }
        // ---- odd sub-phase B: internal (e5,e6) + both boundary halves ----
        {
            float4 OA2 = gOA[s][c][2][lane];
            float4 OA3 = gOA[s][c][3][lane];
            float4 OB1 = gOB[s][c][1][lane];
            bool smR = (lane == 31) && (c < 3);
            bool smL = (lane == 0)  && (c > 0);
#pragma unroll
            for (int r = 0; r < 4; r++) {
                // gather pre-odd neighbor edges (e0 right, e7 left), consumed now
                float nbr = __shfl_down_sync(0xffffffffu, xr[r][0], 1);
                float nbi = __shfl_down_sync(0xffffffffu, xi[r][0], 1);
                float lar = __shfl_up_sync  (0xffffffffu, xr[r][7], 1);
                float lai = __shfl_up_sync  (0xffffffffu, xi[r][7], 1);
                if (smR) { nbr = sE0[par][g][c + 1][r][0]; nbi = sE0[par][g][c + 1][r][1]; }
                if (smL) { lar = sE7[par][g][c - 1][r][0]; lai = sE7[par][g][c - 1][r][1]; }

                // internal pair (e5,e6) — fills shuffle latency
                ROT(xr[r][5], xi[r][5], xr[r][6], xi[r][6], OA2, OB1.x, OB1.y);

                // boundary a'-half: e7 with right neighbor's pre-odd e0
                float ar = xr[r][7], ai = xi[r][7];
                xr[r][7] = ar * OA3.x - ai * OA3.y - nbr * OA3.z + nbi * OA3.w;
                xi[r][7] = ar * OA3.y + ai * OA3.x - nbr * OA3.w - nbi * OA3.z;

                // boundary b'-half: e0 with left neighbor's pre-odd e7
                xr[r][0] = xr[r][0] * OB1.z + lar * OB1.w;
                xi[r][0] = xi[r][0] * OB1.z + lai * OB1.w;
            }
        }
    }

    // ---------------- final diagonal phase + store ----------------
    const float4* omv = (const float4*)g_om;
#pragma unroll
    for (int r = 0; r < 4; r++) {
        float4* o4 = (float4*)(out + (size_t)(row0 + r) * 2048 + ebase * 2);
#pragma unroll
        for (int i = 0; i < 4; i++) {
            float4 m = omv[(ebase >> 1) + i];
            float r0 = xr[r][2*i]   * m.x - xi[r][2*i]   * m.y;
            float i0 = xr[r][2*i]   * m.y + xi[r][2*i]   * m.x;
            float r1 = xr[r][2*i+1] * m.z - xi[r][2*i+1] * m.w;
            float i1 = xr[r][2*i+1] * m.w + xi[r][2*i+1] * m.z;
            o4[i] = make_float4(r0, i0, r1, i1);
        }
    }
}

extern "C" void kernel_launch(void* const* d_in, const int* in_sizes, int n_in,
                              void* d_out, int out_size)
{
    const float* x     = (const float*)d_in[0];
    const float* omega = (const float*)d_in[1];
    const float* et    = (const float*)d_in[2];
    const float* ot    = (const float*)d_in[3];
    const float* ep    = (const float*)d_in[4];
    const float* op    = (const float*)d_in[5];

    eunn_precompute<<<68, 256>>>(omega, et, ot, ep, op);   // 17408 threads

    int rows = in_sizes[0] / 2048;                         // 4096
    eunn_main<<<rows / 8, 256>>>(x, (float*)d_out);        // 8 rows per block
}

// round 9
// speedup vs baseline: 1.2959x; 1.2959x over previous
#include <cuda_runtime.h>
#include <cuda_bf16.h>

#define STEPS 16

// ---- coefficient tables (identical to R7, which passed) ------------------
// Warp slice c (0..3) owns elements [256c, 256c+256); lane L owns the 8
// elements e0..e7 = 256c + 8L + {0..7} of its rows.
// Even pairs  p = 128c + 4L + j, j=0..3 : (e2j, e2j+1)           lane-internal
// Odd  pairs  q = 128c + 4L + j, j=0..2 : (e2j+1, e2j+2)         lane-internal
//             q = 128c + 4L + 3         : (e7, next-lane e0)     boundary
//             q = 128c + 4L - 1         : (left-lane e7, e0)     boundary
// A-tables: (cx, cy, cz, cw) = (sp*ct, cp*ct, sp*st, cp*st)  [a'-update]
// B-tables: packed (ct, st) per pair                          [b'-update]
//   gOB[s][c][1][L] = (ct_q2, st_q2, ct_left, st_left)
// Nonexistent pairs (q=-1, q=511) -> exact identity.
__device__ float4 gEA[STEPS][4][4][32];
__device__ float4 gEB[STEPS][4][2][32];
__device__ float4 gOA[STEPS][4][4][32];
__device__ float4 gOB[STEPS][4][2][32];
__device__ float2 g_om[1024];

__global__ void eunn_precompute(const float* __restrict__ omega,
                                const float* __restrict__ et,
                                const float* __restrict__ ot,
                                const float* __restrict__ ep,
                                const float* __restrict__ op)
{
    int idx = blockIdx.x * blockDim.x + threadIdx.x;
    if (idx < 8192) {
        int s = idx >> 9, p = idx & 511;
        int c = p >> 7, w = p & 127, L = w >> 2, j = w & 3;
        float st, ct, sp, cp;
        sincosf(et[s * 512 + p], &st, &ct);
        sincosf(ep[s * 512 + p], &sp, &cp);
        gEA[s][c][j][L] = make_float4(sp * ct, cp * ct, sp * st, cp * st);
        ((float2*)&gEB[s][c][j >> 1][L])[j & 1] = make_float2(ct, st);
    } else if (idx < 16384) {
        int t = idx - 8192;
        int s = t >> 9, q = t & 511;
        if (q < 511) {                       // NB: ot/op row stride is 511
            int c = q >> 7, w = q & 127, L = w >> 2, j = w & 3;
            float st, ct, sp, cp;
            sincosf(ot[s * 511 + q], &st, &ct);
            sincosf(op[s * 511 + q], &sp, &cp);
            gOA[s][c][j][L] = make_float4(sp * ct, cp * ct, sp * st, cp * st);
            if (j == 0)      ((float2*)&gOB[s][c][0][L])[0] = make_float2(ct, st);
            else if (j == 1) ((float2*)&gOB[s][c][0][L])[1] = make_float2(ct, st);
            else if (j == 2) ((float2*)&gOB[s][c][1][L])[0] = make_float2(ct, st);
            else {
                int q1 = q + 1;
                int cn = q1 >> 7, Ln = (q1 & 127) >> 2;
                ((float2*)&gOB[s][cn][1][Ln])[1] = make_float2(ct, st);
            }
        } else {
            gOA[s][3][3][31] = make_float4(1.f, 0.f, 0.f, 0.f);
            ((float2*)&gOB[s][0][1][0])[1] = make_float2(1.f, 0.f);
        }
    } else if (idx < 17408) {
        int h = idx - 16384;
        float sn, cs;
        sincosf(omega[h], &sn, &cs);
        g_om[h] = make_float2(cs, sn);
    }
}

// full 12-FMA rotation of pair (A, B)
#define ROT(Ar, Ai, Br, Bi, c4, dt, ds)                                    \
    do {                                                                   \
        float _ar = (Ar), _ai = (Ai), _br = (Br), _bi = (Bi);              \
        (Ar) = _ar * (c4).x - _ai * (c4).y - _br * (c4).z + _bi * (c4).w;  \
        (Ai) = _ar * (c4).y + _ai * (c4).x - _br * (c4).w - _bi * (c4).z;  \
        (Br) = _br * (dt) + _ar * (ds);                                    \
        (Bi) = _bi * (dt) + _ai * (ds);                                    \
    } while (0)

#define R 3   // rows per warp (state = 48 regs; 3 CTAs/SM without spilling)

// Block = 256 threads = 2 row-groups (g) x 4 slice-warps (c).
// Warp (g,c), lane L: elements 256c + 8L + {0..7} of rows row0..row0+R-1.
__global__ void __launch_bounds__(256, 3)
eunn_main(const float* __restrict__ x, float* __restrict__ out)
{
    __shared__ float sE0[2][2][4][R][2];   // [parity][g][slice][row][re/im]
    __shared__ float sE7[2][2][4][R][2];

    int lane  = threadIdx.x & 31;
    int wblk  = threadIdx.x >> 5;
    int c     = wblk & 3;
    int g     = wblk >> 2;
    int row0  = blockIdx.x * (2 * R) + g * R;
    int ebase = c * 256 + lane * 8;

    float xr[R][8], xi[R][8];
#pragma unroll
    for (int r = 0; r < R; r++) {
        int row = row0 + r;
        int rowc = row < 4095 ? row : 4095;   // clamp OOB tail rows
        const float4* p4 = (const float4*)(x + (size_t)rowc * 2048 + ebase * 2);
#pragma unroll
        for (int i = 0; i < 4; i++) {
            float4 v = __ldg(&p4[i]);
            xr[r][2*i] = v.x; xi[r][2*i] = v.y; xr[r][2*i+1] = v.z; xi[r][2*i+1] = v.w;
        }
    }

#pragma unroll 1
    for (int s = 0; s < STEPS; s++) {
        int par = s & 1;

        // ---- even sub-phase A: pairs (e0,e1), (e2,e3) ----
        {
            float4 EA0 = gEA[s][c][0][lane];
            float4 EA1 = gEA[s][c][1][lane];
            float4 EB0 = gEB[s][c][0][lane];
#pragma unroll
            for (int r = 0; r < R; r++) {
                ROT(xr[r][0], xi[r][0], xr[r][1], xi[r][1], EA0, EB0.x, EB0.y);
                ROT(xr[r][2], xi[r][2], xr[r][3], xi[r][3], EA1, EB0.z, EB0.w);
            }
        }
        // ---- even sub-phase B: pairs (e4,e5), (e6,e7) ----
        {
            float4 EA2 = gEA[s][c][2][lane];
            float4 EA3 = gEA[s][c][3][lane];
            float4 EB1 = gEB[s][c][1][lane];
#pragma unroll
            for (int r = 0; r < R; r++) {
                ROT(xr[r][4], xi[r][4], xr[r][5], xi[r][5], EA2, EB1.x, EB1.y);
                ROT(xr[r][6], xi[r][6], xr[r][7], xi[r][7], EA3, EB1.z, EB1.w);
            }
        }

        // publish post-even slice edges
        if (lane == 0) {
#pragma unroll
            for (int r = 0; r < R; r++) {
                sE0[par][g][c][r][0] = xr[r][0];
                sE0[par][g][c][r][1] = xi[r][0];
            }
        }
        if (lane == 31) {
#pragma unroll
            for (int r = 0; r < R; r++) {
                sE7[par][g][c][r][0] = xr[r][7];
                sE7[par][g][c][r][1] = xi[r][7];
            }
        }
        asm volatile("bar.sync %0, 128;" :: "r"(g + 1) : "memory");

        // ---- odd sub-phase A: internal pairs (e1,e2), (e3,e4) ----
        {
            float4 OA0 = gOA[s][c][0][lane];
            float4 OA1 = gOA[s][c][1][lane];
            float4 OB0 = gOB[s][c][0][lane];
#pragma unroll
            for (int r = 0; r < R; r++) {
                ROT(xr[r][1], xi[r][1], xr[r][2], xi[r][2], OA0, OB0.x, OB0.y);
                ROT(xr[r][3], xi[r][3], xr[r][4], xi[r][4], OA1, OB0.z, OB0.w);
            }
        }
        // ---- odd sub-phase B: internal (e5,e6) + both boundary halves ----
        {
            float4 OA2 = gOA[s][c][2][lane];
            float4 OA3 = gOA[s][c][3][lane];
            float4 OB1 = gOB[s][c][1][lane];
            bool smR = (lane == 31) && (c < 3);
            bool smL = (lane == 0)  && (c > 0);
#pragma unroll
            for (int r = 0; r < R; r++) {
                // gather pre-odd neighbor edges (e0 right, e7 left), consumed now
                float nbr = __shfl_down_sync(0xffffffffu, xr[r][0], 1);
                float nbi = __shfl_down_sync(0xffffffffu, xi[r][0], 1);
                float lar = __shfl_up_sync  (0xffffffffu, xr[r][7], 1);
                float lai = __shfl_up_sync  (0xffffffffu, xi[r][7], 1);
                if (smR) { nbr = sE0[par][g][c + 1][r][0]; nbi = sE0[par][g][c + 1][r][1]; }
                if (smL) { lar = sE7[par][g][c - 1][r][0]; lai = sE7[par][g][c - 1][r][1]; }

                // internal pair (e5,e6) — fills shuffle latency
                ROT(xr[r][5], xi[r][5], xr[r][6], xi[r][6], OA2, OB1.x, OB1.y);

                // boundary a'-half: e7 with right neighbor's pre-odd e0
                float ar = xr[r][7], ai = xi[r][7];
                xr[r][7] = ar * OA3.x - ai * OA3.y - nbr * OA3.z + nbi * OA3.w;
                xi[r][7] = ar * OA3.y + ai * OA3.x - nbr * OA3.w - nbi * OA3.z;

                // boundary b'-half: e0 with left neighbor's pre-odd e7
                xr[r][0] = xr[r][0] * OB1.z + lar * OB1.w;
                xi[r][0] = xi[r][0] * OB1.z + lai * OB1.w;
            }
        }
    }

    // ---------------- final diagonal phase + store ----------------
    const float4* omv = (const float4*)g_om;
#pragma unroll
    for (int r = 0; r < R; r++) {
        int row = row0 + r;
        if (row < 4096) {
            float4* o4 = (float4*)(out + (size_t)row * 2048 + ebase * 2);
#pragma unroll
            for (int i = 0; i < 4; i++) {
                float4 m = omv[(ebase >> 1) + i];
                float r0 = xr[r][2*i]   * m.x - xi[r][2*i]   * m.y;
                float i0 = xr[r][2*i]   * m.y + xi[r][2*i]   * m.x;
                float r1 = xr[r][2*i+1] * m.z - xi[r][2*i+1] * m.w;
                float i1 = xr[r][2*i+1] * m.w + xi[r][2*i+1] * m.z;
                o4[i] = make_float4(r0, i0, r1, i1);
            }
        }
    }
}

extern "C" void kernel_launch(void* const* d_in, const int* in_sizes, int n_in,
                              void* d_out, int out_size)
{
    const float* x     = (const float*)d_in[0];
    const float* omega = (const float*)d_in[1];
    const float* et    = (const float*)d_in[2];
    const float* ot    = (const float*)d_in[3];
    const float* ep    = (const float*)d_in[4];
    const float* op    = (const float*)d_in[5];

    eunn_precompute<<<68, 256>>>(omega, et, ot, ep, op);   // 17408 threads

    int rows = in_sizes[0] / 2048;                         // 4096
    int rpb  = 2 * R;                                      // rows per block
    eunn_main<<<(rows + rpb - 1) / rpb, 256>>>(x, (float*)d_out);
}

// round 10
// speedup vs baseline: 1.9598x; 1.5123x over previous
#include <cuda_runtime.h>
#include <cuda_bf16.h>

#define STEPS 16

// ---- coefficient tables ---------------------------------------------------
// Factorized rotation: pair (a,b):  t = a*ct - b*st ; b' = a*st + b*ct ;
//                                   a' = w*t,  w = sp + i*cp.
// Tables store raw (ct, st, sp, cp) per pair -> 16B instead of 24B.
//
// Warp slice c (0..3) owns elements [256c, 256c+256); lane L owns e0..e7 =
// 256c + 8L + {0..7} of its 4 rows.
// Even pairs  p = 128c + 4L + j, j=0..3 : (e2j, e2j+1)        lane-internal
// Odd  pairs  q = 128c + 4L + j, j=0..2 : (e2j+1, e2j+2)      lane-internal
//             q = 128c + 4L + 3         : (e7, next e0)       boundary a'-half
//             q = 128c + 4L - 1         : (prev e7, e0)       boundary b'-half
// gOL[s][c][L] = (ct, st) of the left-boundary pair q = 128c+4L-1.
// Nonexistent pairs (q=-1, q=511) -> exact identity (ct=1,st=0,sp=1,cp=0).
__device__ float4 gE [STEPS][4][4][32];
__device__ float4 gO [STEPS][4][4][32];
__device__ float2 gOL[STEPS][4][32];
__device__ float2 g_om[1024];

__global__ void eunn_precompute(const float* __restrict__ omega,
                                const float* __restrict__ et,
                                const float* __restrict__ ot,
                                const float* __restrict__ ep,
                                const float* __restrict__ op)
{
    int idx = blockIdx.x * blockDim.x + threadIdx.x;
    if (idx < 8192) {
        // even pair p
        int s = idx >> 9, p = idx & 511;
        int c = p >> 7, w = p & 127, L = w >> 2, j = w & 3;
        float st, ct, sp, cp;
        sincosf(et[s * 512 + p], &st, &ct);
        sincosf(ep[s * 512 + p], &sp, &cp);
        gE[s][c][j][L] = make_float4(ct, st, sp, cp);
    } else if (idx < 16384) {
        // odd pair q   (NB: ot/op row stride is 511)
        int t = idx - 8192;
        int s = t >> 9, q = t & 511;
        if (q < 511) {
            int c = q >> 7, w = q & 127, L = w >> 2, j = w & 3;
            float st, ct, sp, cp;
            sincosf(ot[s * 511 + q], &st, &ct);
            sincosf(op[s * 511 + q], &sp, &cp);
            gO[s][c][j][L] = make_float4(ct, st, sp, cp);
            if (j == 3) {
                // also the LEFT-boundary (b'-half) pair of the next lane
                int q1 = q + 1;
                int cn = q1 >> 7, Ln = (q1 & 127) >> 2;
                gOL[s][cn][Ln] = make_float2(ct, st);
            }
        } else {
            // q == 511 doesn't exist: identity both places
            gO[s][3][3][31] = make_float4(1.f, 0.f, 1.f, 0.f);
            gOL[s][0][0]    = make_float2(1.f, 0.f);
        }
    } else if (idx < 17408) {
        int h = idx - 16384;
        float sn, cs;
        sincosf(omega[h], &sn, &cs);
        g_om[h] = make_float2(cs, sn);
    }
}

// 12-FMA factorized rotation; C = (ct, st, sp, cp)
#define ROT(Ar, Ai, Br, Bi, C)                                   \
    do {                                                         \
        float _tr = (Ar) * (C).x - (Br) * (C).y;                 \
        float _ti = (Ai) * (C).x - (Bi) * (C).y;                 \
        float _br = (Br) * (C).x + (Ar) * (C).y;                 \
        float _bi = (Bi) * (C).x + (Ai) * (C).y;                 \
        (Br) = _br; (Bi) = _bi;                                  \
        (Ar) = _tr * (C).z - _ti * (C).w;                        \
        (Ai) = _tr * (C).w + _ti * (C).z;                        \
    } while (0)

// Block = 256 threads = 2 row-groups (g) x 4 slice-warps (c).
// Warp (g,c), lane L: elements 256c + 8L + {0..7} of rows row0..row0+3.
__global__ void __launch_bounds__(256, 2)
eunn_main(const float* __restrict__ x, float* __restrict__ out)
{
    __shared__ float sE0[2][2][4][4][2];   // [parity][g][slice][row][re/im]
    __shared__ float sE7[2][2][4][4][2];

    int lane  = threadIdx.x & 31;
    int wblk  = threadIdx.x >> 5;
    int c     = wblk & 3;
    int g     = wblk >> 2;
    int row0  = blockIdx.x * 8 + g * 4;
    int ebase = c * 256 + lane * 8;

    float xr[4][8], xi[4][8];
#pragma unroll
    for (int r = 0; r < 4; r++) {
        const float4* p4 = (const float4*)(x + (size_t)(row0 + r) * 2048 + ebase * 2);
#pragma unroll
        for (int i = 0; i < 4; i++) {
            float4 v = __ldg(&p4[i]);
            xr[r][2*i] = v.x; xi[r][2*i] = v.y; xr[r][2*i+1] = v.z; xi[r][2*i+1] = v.w;
        }
    }

#pragma unroll 1
    for (int s = 0; s < STEPS; s++) {
        int par = s & 1;

        // all 9 coefficient loads issued up-front (MLP; odd-phase loads'
        // latency is covered by the even-phase compute)
        float4 E0 = gE[s][c][0][lane], E1 = gE[s][c][1][lane];
        float4 E2 = gE[s][c][2][lane], E3 = gE[s][c][3][lane];
        float4 O0 = gO[s][c][0][lane], O1 = gO[s][c][1][lane];
        float4 O2 = gO[s][c][2][lane], O3 = gO[s][c][3][lane];
        float2 OL = gOL[s][c][lane];

        // ---------------- even sweep: 4 lane-internal pairs ----------------
#pragma unroll
        for (int r = 0; r < 4; r++) {
            ROT(xr[r][0], xi[r][0], xr[r][1], xi[r][1], E0);
            ROT(xr[r][2], xi[r][2], xr[r][3], xi[r][3], E1);
            ROT(xr[r][4], xi[r][4], xr[r][5], xi[r][5], E2);
            ROT(xr[r][6], xi[r][6], xr[r][7], xi[r][7], E3);
        }

        // publish post-even slice edges
        if (lane == 0) {
#pragma unroll
            for (int r = 0; r < 4; r++) {
                sE0[par][g][c][r][0] = xr[r][0];
                sE0[par][g][c][r][1] = xi[r][0];
            }
        }
        if (lane == 31) {
#pragma unroll
            for (int r = 0; r < 4; r++) {
                sE7[par][g][c][r][0] = xr[r][7];
                sE7[par][g][c][r][1] = xi[r][7];
            }
        }
        asm volatile("bar.sync %0, 128;" :: "r"(g + 1) : "memory");

        // batched neighbor gather (pre-odd values): right e0, left e7
        float nbr[4], nbi[4], lar[4], lai[4];
#pragma unroll
        for (int r = 0; r < 4; r++) {
            nbr[r] = __shfl_down_sync(0xffffffffu, xr[r][0], 1);
            nbi[r] = __shfl_down_sync(0xffffffffu, xi[r][0], 1);
            lar[r] = __shfl_up_sync  (0xffffffffu, xr[r][7], 1);
            lai[r] = __shfl_up_sync  (0xffffffffu, xi[r][7], 1);
        }
        if (lane == 31 && c < 3) {
#pragma unroll
            for (int r = 0; r < 4; r++) {
                nbr[r] = sE0[par][g][c + 1][r][0];
                nbi[r] = sE0[par][g][c + 1][r][1];
            }
        }
        if (lane == 0 && c > 0) {
#pragma unroll
            for (int r = 0; r < 4; r++) {
                lar[r] = sE7[par][g][c - 1][r][0];
                lai[r] = sE7[par][g][c - 1][r][1];
            }
        }

        // ---------------- odd sweep (all pairs disjoint) ----------------
#pragma unroll
        for (int r = 0; r < 4; r++) {
            ROT(xr[r][1], xi[r][1], xr[r][2], xi[r][2], O0);
            ROT(xr[r][3], xi[r][3], xr[r][4], xi[r][4], O1);
            ROT(xr[r][5], xi[r][5], xr[r][6], xi[r][6], O2);
            // boundary a'-half: e7 with right neighbor's pre-odd e0
            float tr = xr[r][7] * O3.x - nbr[r] * O3.y;
            float ti = xi[r][7] * O3.x - nbi[r] * O3.y;
            xr[r][7] = tr * O3.z - ti * O3.w;
            xi[r][7] = tr * O3.w + ti * O3.z;
            // boundary b'-half: e0 with left neighbor's pre-odd e7
            xr[r][0] = xr[r][0] * OL.x + lar[r] * OL.y;
            xi[r][0] = xi[r][0] * OL.x + lai[r] * OL.y;
        }
    }

    // ---------------- final diagonal phase + store ----------------
    const float4* omv = (const float4*)g_om;
#pragma unroll
    for (int r = 0; r < 4; r++) {
        float4* o4 = (float4*)(out + (size_t)(row0 + r) * 2048 + ebase * 2);
#pragma unroll
        for (int i = 0; i < 4; i++) {
            float4 m = omv[(ebase >> 1) + i];
            float r0 = xr[r][2*i]   * m.x - xi[r][2*i]   * m.y;
            float i0 = xr[r][2*i]   * m.y + xi[r][2*i]   * m.x;
            float r1 = xr[r][2*i+1] * m.z - xi[r][2*i+1] * m.w;
            float i1 = xr[r][2*i+1] * m.w + xi[r][2*i+1] * m.z;
            o4[i] = make_float4(r0, i0, r1, i1);
        }
    }
}

extern "C" void kernel_launch(void* const* d_in, const int* in_sizes, int n_in,
                              void* d_out, int out_size)
{
    const float* x     = (const float*)d_in[0];
    const float* omega = (const float*)d_in[1];
    const float* et    = (const float*)d_in[2];
    const float* ot    = (const float*)d_in[3];
    const float* ep    = (const float*)d_in[4];
    const float* op    = (const float*)d_in[5];

    eunn_precompute<<<68, 256>>>(omega, et, ot, ep, op);   // 17408 threads

    int rows = in_sizes[0] / 2048;                         // 4096
    eunn_main<<<rows / 8, 256>>>(x, (float*)d_out);        // 8 rows per block
}

// round 11
// speedup vs baseline: 1.9769x; 1.0087x over previous
#include <cuda_runtime.h>
#include <cuda_bf16.h>

#define STEPS 16

// ---- coefficient tables (identical to R10, which passed) ------------------
// Factorized rotation: pair (a,b):  t = a*ct - b*st ; b' = a*st + b*ct ;
//                                   a' = w*t,  w = sp + i*cp.
// Tables store raw (ct, st, sp, cp) per pair.
// Warp slice c (0..3) owns elements [256c, 256c+256); lane L owns e0..e7 =
// 256c + 8L + {0..7} of its 4 rows.
// Even pairs  p = 128c + 4L + j, j=0..3 : (e2j, e2j+1)        lane-internal
// Odd  pairs  q = 128c + 4L + j, j=0..2 : (e2j+1, e2j+2)      lane-internal
//             q = 128c + 4L + 3         : (e7, next e0)       boundary a'-half
//             q = 128c + 4L - 1         : (prev e7, e0)       boundary b'-half
// gOL[s][c][L] = (ct, st) of the left-boundary pair q = 128c+4L-1.
// Nonexistent pairs (q=-1, q=511) -> exact identity.
__device__ float4 gE [STEPS][4][4][32];
__device__ float4 gO [STEPS][4][4][32];
__device__ float2 gOL[STEPS][4][32];
__device__ float2 g_om[1024];

__global__ void eunn_precompute(const float* __restrict__ omega,
                                const float* __restrict__ et,
                                const float* __restrict__ ot,
                                const float* __restrict__ ep,
                                const float* __restrict__ op)
{
    int idx = blockIdx.x * blockDim.x + threadIdx.x;
    if (idx < 8192) {
        // even pair p
        int s = idx >> 9, p = idx & 511;
        int c = p >> 7, w = p & 127, L = w >> 2, j = w & 3;
        float st, ct, sp, cp;
        sincosf(et[s * 512 + p], &st, &ct);
        sincosf(ep[s * 512 + p], &sp, &cp);
        gE[s][c][j][L] = make_float4(ct, st, sp, cp);
    } else if (idx < 16384) {
        // odd pair q   (NB: ot/op row stride is 511)
        int t = idx - 8192;
        int s = t >> 9, q = t & 511;
        if (q < 511) {
            int c = q >> 7, w = q & 127, L = w >> 2, j = w & 3;
            float st, ct, sp, cp;
            sincosf(ot[s * 511 + q], &st, &ct);
            sincosf(op[s * 511 + q], &sp, &cp);
            gO[s][c][j][L] = make_float4(ct, st, sp, cp);
            if (j == 3) {
                // also the LEFT-boundary (b'-half) pair of the next lane
                int q1 = q + 1;
                int cn = q1 >> 7, Ln = (q1 & 127) >> 2;
                gOL[s][cn][Ln] = make_float2(ct, st);
            }
        } else {
            // q == 511 doesn't exist: identity both places
            gO[s][3][3][31] = make_float4(1.f, 0.f, 1.f, 0.f);
            gOL[s][0][0]    = make_float2(1.f, 0.f);
        }
    } else if (idx < 17408) {
        int h = idx - 16384;
        float sn, cs;
        sincosf(omega[h], &sn, &cs);
        g_om[h] = make_float2(cs, sn);
    }
}

// 12-FMA factorized rotation; C = (ct, st, sp, cp)
#define ROT(Ar, Ai, Br, Bi, C)                                   \
    do {                                                         \
        float _tr = (Ar) * (C).x - (Br) * (C).y;                 \
        float _ti = (Ai) * (C).x - (Bi) * (C).y;                 \
        float _br = (Br) * (C).x + (Ar) * (C).y;                 \
        float _bi = (Bi) * (C).x + (Ai) * (C).y;                 \
        (Br) = _br; (Bi) = _bi;                                  \
        (Ar) = _tr * (C).z - _ti * (C).w;                        \
        (Ai) = _tr * (C).w + _ti * (C).z;                        \
    } while (0)

// Block = 256 threads = 2 row-groups (g) x 4 slice-warps (c).
// Warp (g,c), lane L: elements 256c + 8L + {0..7} of rows row0..row0+3.
// Loads are software-pipelined: odd coeffs at step-top (hidden under the
// even sweep), NEXT step's even coeffs after the barrier (hidden under the
// odd sweep). No exposed LDG latency in steady state.
__global__ void __launch_bounds__(256, 2)
eunn_main(const float* __restrict__ x, float* __restrict__ out)
{
    __shared__ float sE0[2][2][4][4][2];   // [parity][g][slice][row][re/im]
    __shared__ float sE7[2][2][4][4][2];

    int lane  = threadIdx.x & 31;
    int wblk  = threadIdx.x >> 5;
    int c     = wblk & 3;
    int g     = wblk >> 2;
    int row0  = blockIdx.x * 8 + g * 4;
    int ebase = c * 256 + lane * 8;

    float xr[4][8], xi[4][8];
#pragma unroll
    for (int r = 0; r < 4; r++) {
        const float4* p4 = (const float4*)(x + (size_t)(row0 + r) * 2048 + ebase * 2);
#pragma unroll
        for (int i = 0; i < 4; i++) {
            float4 v = __ldg(&p4[i]);
            xr[r][2*i] = v.x; xi[r][2*i] = v.y; xr[r][2*i+1] = v.z; xi[r][2*i+1] = v.w;
        }
    }

    // prologue: even coefficients for step 0
    float4 E0 = gE[0][c][0][lane], E1 = gE[0][c][1][lane];
    float4 E2 = gE[0][c][2][lane], E3 = gE[0][c][3][lane];

#pragma unroll 1
    for (int s = 0; s < STEPS; s++) {
        int par = s & 1;

        // odd coefficients for THIS step: latency hidden under even sweep
        float4 O0 = gO[s][c][0][lane], O1 = gO[s][c][1][lane];
        float4 O2 = gO[s][c][2][lane], O3 = gO[s][c][3][lane];
        float2 OL = gOL[s][c][lane];

        // ---------------- even sweep: 4 lane-internal pairs ----------------
#pragma unroll
        for (int r = 0; r < 4; r++) {
            ROT(xr[r][0], xi[r][0], xr[r][1], xi[r][1], E0);
            ROT(xr[r][2], xi[r][2], xr[r][3], xi[r][3], E1);
            ROT(xr[r][4], xi[r][4], xr[r][5], xi[r][5], E2);
            ROT(xr[r][6], xi[r][6], xr[r][7], xi[r][7], E3);
        }

        // publish post-even slice edges
        if (lane == 0) {
#pragma unroll
            for (int r = 0; r < 4; r++) {
                sE0[par][g][c][r][0] = xr[r][0];
                sE0[par][g][c][r][1] = xi[r][0];
            }
        }
        if (lane == 31) {
#pragma unroll
            for (int r = 0; r < 4; r++) {
                sE7[par][g][c][r][0] = xr[r][7];
                sE7[par][g][c][r][1] = xi[r][7];
            }
        }
        asm volatile("bar.sync %0, 128;" :: "r"(g + 1) : "memory");

        // prefetch NEXT step's even coefficients: hidden under odd sweep
        int sn = (s + 1 < STEPS) ? s + 1 : s;
        E0 = gE[sn][c][0][lane]; E1 = gE[sn][c][1][lane];
        E2 = gE[sn][c][2][lane]; E3 = gE[sn][c][3][lane];

        // ---------------- odd sweep (per-row gather, consumed immediately) --
        bool smR = (lane == 31) && (c < 3);
        bool smL = (lane == 0)  && (c > 0);
#pragma unroll
        for (int r = 0; r < 4; r++) {
            // neighbor pre-odd edges: right e0, left e7
            float nbr = __shfl_down_sync(0xffffffffu, xr[r][0], 1);
            float nbi = __shfl_down_sync(0xffffffffu, xi[r][0], 1);
            float lar = __shfl_up_sync  (0xffffffffu, xr[r][7], 1);
            float lai = __shfl_up_sync  (0xffffffffu, xi[r][7], 1);
            if (smR) { nbr = sE0[par][g][c + 1][r][0]; nbi = sE0[par][g][c + 1][r][1]; }
            if (smL) { lar = sE7[par][g][c - 1][r][0]; lai = sE7[par][g][c - 1][r][1]; }

            // internal pairs — fill shuffle latency
            ROT(xr[r][1], xi[r][1], xr[r][2], xi[r][2], O0);
            ROT(xr[r][3], xi[r][3], xr[r][4], xi[r][4], O1);
            ROT(xr[r][5], xi[r][5], xr[r][6], xi[r][6], O2);

            // boundary a'-half: e7 with right neighbor's pre-odd e0
            float tr = xr[r][7] * O3.x - nbr * O3.y;
            float ti = xi[r][7] * O3.x - nbi * O3.y;
            xr[r][7] = tr * O3.z - ti * O3.w;
            xi[r][7] = tr * O3.w + ti * O3.z;

            // boundary b'-half: e0 with left neighbor's pre-odd e7
            xr[r][0] = xr[r][0] * OL.x + lar * OL.y;
            xi[r][0] = xi[r][0] * OL.x + lai * OL.y;
        }
    }

    // ---------------- final diagonal phase + store ----------------
    const float4* omv = (const float4*)g_om;
#pragma unroll
    for (int r = 0; r < 4; r++) {
        float4* o4 = (float4*)(out + (size_t)(row0 + r) * 2048 + ebase * 2);
#pragma unroll
        for (int i = 0; i < 4; i++) {
            float4 m = omv[(ebase >> 1) + i];
            float r0 = xr[r][2*i]   * m.x - xi[r][2*i]   * m.y;
            float i0 = xr[r][2*i]   * m.y + xi[r][2*i]   * m.x;
            float r1 = xr[r][2*i+1] * m.z - xi[r][2*i+1] * m.w;
            float i1 = xr[r][2*i+1] * m.w + xi[r][2*i+1] * m.z;
            o4[i] = make_float4(r0, i0, r1, i1);
        }
    }
}

extern "C" void kernel_launch(void* const* d_in, const int* in_sizes, int n_in,
                              void* d_out, int out_size)
{
    const float* x     = (const float*)d_in[0];
    const float* omega = (const float*)d_in[1];
    const float* et    = (const float*)d_in[2];
    const float* ot    = (const float*)d_in[3];
    const float* ep    = (const float*)d_in[4];
    const float* op    = (const float*)d_in[5];

    eunn_precompute<<<68, 256>>>(omega, et, ot, ep, op);   // 17408 threads

    int rows = in_sizes[0] / 2048;                         // 4096
    eunn_main<<<rows / 8, 256>>>(x, (float*)d_out);        // 8 rows per block
}

// round 12
// speedup vs baseline: 2.1152x; 1.0700x over previous
#include <cuda_runtime.h>
#include <cuda_bf16.h>

#define STEPS 16

// ---- coefficient tables (identical layout to R10/R11, which passed) -------
// Factorized rotation: pair (a,b):  t = a*ct - b*st ; b' = a*st + b*ct ;
//                                   a' = w*t,  w = sp + i*cp.
// Tables store raw (ct, st, sp, cp) per pair.
// Warp slice c (0..3) owns elements [256c, 256c+256); lane L owns e0..e7 =
// 256c + 8L + {0..7} of its rows.
// Even pairs  p = 128c + 4L + j, j=0..3 : (e2j, e2j+1)        lane-internal
// Odd  pairs  q = 128c + 4L + j, j=0..2 : (e2j+1, e2j+2)      lane-internal
//             q = 128c + 4L + 3         : (e7, next e0)       boundary a'-half
//             q = 128c + 4L - 1         : (prev e7, e0)       boundary b'-half
// gOL[s][c][L] = (ct, st) of the left-boundary pair q = 128c+4L-1.
// Nonexistent pairs (q=-1, q=511) -> exact identity.
__device__ float4 gE [STEPS][4][4][32];
__device__ float4 gO [STEPS][4][4][32];
__device__ float2 gOL[STEPS][4][32];
__device__ float2 g_om[1024];

__global__ void eunn_precompute(const float* __restrict__ omega,
                                const float* __restrict__ et,
                                const float* __restrict__ ot,
                                const float* __restrict__ ep,
                                const float* __restrict__ op)
{
    int idx = blockIdx.x * blockDim.x + threadIdx.x;
    if (idx < 8192) {
        // even pair p
        int s = idx >> 9, p = idx & 511;
        int c = p >> 7, w = p & 127, L = w >> 2, j = w & 3;
        float st, ct, sp, cp;
        __sincosf(et[s * 512 + p], &st, &ct);
        __sincosf(ep[s * 512 + p], &sp, &cp);
        gE[s][c][j][L] = make_float4(ct, st, sp, cp);
    } else if (idx < 16384) {
        // odd pair q   (NB: ot/op row stride is 511)
        int t = idx - 8192;
        int s = t >> 9, q = t & 511;
        if (q < 511) {
            int c = q >> 7, w = q & 127, L = w >> 2, j = w & 3;
            float st, ct, sp, cp;
            __sincosf(ot[s * 511 + q], &st, &ct);
            __sincosf(op[s * 511 + q], &sp, &cp);
            gO[s][c][j][L] = make_float4(ct, st, sp, cp);
            if (j == 3) {
                // also the LEFT-boundary (b'-half) pair of the next lane
                int q1 = q + 1;
                int cn = q1 >> 7, Ln = (q1 & 127) >> 2;
                gOL[s][cn][Ln] = make_float2(ct, st);
            }
        } else {
            // q == 511 doesn't exist: identity both places
            gO[s][3][3][31] = make_float4(1.f, 0.f, 1.f, 0.f);
            gOL[s][0][0]    = make_float2(1.f, 0.f);
        }
    } else if (idx < 17408) {
        int h = idx - 16384;
        float sn, cs;
        __sincosf(omega[h], &sn, &cs);
        g_om[h] = make_float2(cs, sn);
    }
}

// 12-FMA factorized rotation; C = (ct, st, sp, cp)
#define ROT(Ar, Ai, Br, Bi, C)                                   \
    do {                                                         \
        float _tr = (Ar) * (C).x - (Br) * (C).y;                 \
        float _ti = (Ai) * (C).x - (Bi) * (C).y;                 \
        float _br = (Br) * (C).x + (Ar) * (C).y;                 \
        float _bi = (Bi) * (C).x + (Ai) * (C).y;                 \
        (Br) = _br; (Bi) = _bi;                                  \
        (Ar) = _tr * (C).z - _ti * (C).w;                        \
        (Ai) = _tr * (C).w + _ti * (C).z;                        \
    } while (0)

// 16-step scan for R rows held in registers. Structure identical to R11's
// loop (software-pipelined coefficient loads, one named barrier per step,
// parity-double-buffered smem edges, symmetric boundary halves).
template<int R>
__device__ __forceinline__ void eunn_steps(
    float (&xr)[4][8], float (&xi)[4][8],
    float (&sE0)[2][2][4][4][2], float (&sE7)[2][2][4][4][2],
    int lane, int c, int g)
{
    // prologue: even coefficients for step 0
    float4 E0 = gE[0][c][0][lane], E1 = gE[0][c][1][lane];
    float4 E2 = gE[0][c][2][lane], E3 = gE[0][c][3][lane];

#pragma unroll 1
    for (int s = 0; s < STEPS; s++) {
        int par = s & 1;

        // odd coefficients for THIS step: latency hidden under even sweep
        float4 O0 = gO[s][c][0][lane], O1 = gO[s][c][1][lane];
        float4 O2 = gO[s][c][2][lane], O3 = gO[s][c][3][lane];
        float2 OL = gOL[s][c][lane];

        // ---------------- even sweep: 4 lane-internal pairs ----------------
#pragma unroll
        for (int r = 0; r < R; r++) {
            ROT(xr[r][0], xi[r][0], xr[r][1], xi[r][1], E0);
            ROT(xr[r][2], xi[r][2], xr[r][3], xi[r][3], E1);
            ROT(xr[r][4], xi[r][4], xr[r][5], xi[r][5], E2);
            ROT(xr[r][6], xi[r][6], xr[r][7], xi[r][7], E3);
        }

        // publish post-even slice edges
        if (lane == 0) {
#pragma unroll
            for (int r = 0; r < R; r++) {
                sE0[par][g][c][r][0] = xr[r][0];
                sE0[par][g][c][r][1] = xi[r][0];
            }
        }
        if (lane == 31) {
#pragma unroll
            for (int r = 0; r < R; r++) {
                sE7[par][g][c][r][0] = xr[r][7];
                sE7[par][g][c][r][1] = xi[r][7];
            }
        }
        asm volatile("bar.sync %0, 128;" :: "r"(g + 1) : "memory");

        // prefetch NEXT step's even coefficients: hidden under odd sweep
        int sn = (s + 1 < STEPS) ? s + 1 : s;
        E0 = gE[sn][c][0][lane]; E1 = gE[sn][c][1][lane];
        E2 = gE[sn][c][2][lane]; E3 = gE[sn][c][3][lane];

        // ---------------- odd sweep (per-row gather, consumed immediately) --
        bool smR = (lane == 31) && (c < 3);
        bool smL = (lane == 0)  && (c > 0);
#pragma unroll
        for (int r = 0; r < R; r++) {
            // neighbor pre-odd edges: right e0, left e7
            float nbr = __shfl_down_sync(0xffffffffu, xr[r][0], 1);
            float nbi = __shfl_down_sync(0xffffffffu, xi[r][0], 1);
            float lar = __shfl_up_sync  (0xffffffffu, xr[r][7], 1);
            float lai = __shfl_up_sync  (0xffffffffu, xi[r][7], 1);
            if (smR) { nbr = sE0[par][g][c + 1][r][0]; nbi = sE0[par][g][c + 1][r][1]; }
            if (smL) { lar = sE7[par][g][c - 1][r][0]; lai = sE7[par][g][c - 1][r][1]; }

            // internal pairs — fill shuffle latency
            ROT(xr[r][1], xi[r][1], xr[r][2], xi[r][2], O0);
            ROT(xr[r][3], xi[r][3], xr[r][4], xi[r][4], O1);
            ROT(xr[r][5], xi[r][5], xr[r][6], xi[r][6], O2);

            // boundary a'-half: e7 with right neighbor's pre-odd e0
            float tr = xr[r][7] * O3.x - nbr * O3.y;
            float ti = xi[r][7] * O3.x - nbi * O3.y;
            xr[r][7] = tr * O3.z - ti * O3.w;
            xi[r][7] = tr * O3.w + ti * O3.z;

            // boundary b'-half: e0 with left neighbor's pre-odd e7
            xr[r][0] = xr[r][0] * OL.x + lar * OL.y;
            xi[r][0] = xi[r][0] * OL.x + lai * OL.y;
        }
    }
}

// One single wave: grid = 296 CTAs = 148 SMs x 2 resident. Each g-group
// (4 slice-warps) owns 7 contiguous rows (last 48 groups: 6), processed as
// batch A = 4 rows then batch B = 3 (or 2, masked) rows. No wave-2 tail.
__global__ void __launch_bounds__(256, 2)
eunn_main(const float* __restrict__ x, float* __restrict__ out)
{
    __shared__ float sE0[2][2][4][4][2];   // [parity][g][slice][row][re/im]
    __shared__ float sE7[2][2][4][4][2];

    int lane  = threadIdx.x & 31;
    int wblk  = threadIdx.x >> 5;
    int c     = wblk & 3;
    int g     = wblk >> 2;
    int ebase = c * 256 + lane * 8;

    int gid = blockIdx.x * 2 + g;          // 0..591
    int row0, nB;
    if (gid < 544) { row0 = gid * 7;                  nB = 3; }
    else           { row0 = 3808 + (gid - 544) * 6;   nB = 2; }

    const float4* omv = (const float4*)g_om;
    float xr[4][8], xi[4][8];

    // =========================== batch A: 4 rows ===========================
#pragma unroll
    for (int r = 0; r < 4; r++) {
        const float4* p4 = (const float4*)(x + (size_t)(row0 + r) * 2048 + ebase * 2);
#pragma unroll
        for (int i = 0; i < 4; i++) {
            float4 v = __ldg(&p4[i]);
            xr[r][2*i] = v.x; xi[r][2*i] = v.y; xr[r][2*i+1] = v.z; xi[r][2*i+1] = v.w;
        }
    }

    eunn_steps<4>(xr, xi, sE0, sE7, lane, c, g);

#pragma unroll
    for (int r = 0; r < 4; r++) {
        float4* o4 = (float4*)(out + (size_t)(row0 + r) * 2048 + ebase * 2);
#pragma unroll
        for (int i = 0; i < 4; i++) {
            float4 m = omv[(ebase >> 1) + i];
            float r0 = xr[r][2*i]   * m.x - xi[r][2*i]   * m.y;
            float i0 = xr[r][2*i]   * m.y + xi[r][2*i]   * m.x;
            float r1 = xr[r][2*i+1] * m.z - xi[r][2*i+1] * m.w;
            float i1 = xr[r][2*i+1] * m.w + xi[r][2*i+1] * m.z;
            o4[i] = make_float4(r0, i0, r1, i1);
        }
    }

    // ========================= batch B: nB (2-3) rows ======================
    int rowB = row0 + 4;
#pragma unroll
    for (int r = 0; r < 3; r++) {
        int rr = rowB + (r < nB ? r : nB - 1);   // clamp: duplicate last valid row
        const float4* p4 = (const float4*)(x + (size_t)rr * 2048 + ebase * 2);
#pragma unroll
        for (int i = 0; i < 4; i++) {
            float4 v = __ldg(&p4[i]);
            xr[r][2*i] = v.x; xi[r][2*i] = v.y; xr[r][2*i+1] = v.z; xi[r][2*i+1] = v.w;
        }
    }

    eunn_steps<3>(xr, xi, sE0, sE7, lane, c, g);

#pragma unroll
    for (int r = 0; r < 3; r++) {
        if (r < nB) {
            float4* o4 = (float4*)(out + (size_t)(rowB + r) * 2048 + ebase * 2);
#pragma unroll
            for (int i = 0; i < 4; i++) {
                float4 m = omv[(ebase >> 1) + i];
                float r0 = xr[r][2*i]   * m.x - xi[r][2*i]   * m.y;
                float i0 = xr[r][2*i]   * m.y + xi[r][2*i]   * m.x;
                float r1 = xr[r][2*i+1] * m.z - xi[r][2*i+1] * m.w;
                float i1 = xr[r][2*i+1] * m.w + xi[r][2*i+1] * m.z;
                o4[i] = make_float4(r0, i0, r1, i1);
            }
        }
    }
}

extern "C" void kernel_launch(void* const* d_in, const int* in_sizes, int n_in,
                              void* d_out, int out_size)
{
    const float* x     = (const float*)d_in[0];
    const float* omega = (const float*)d_in[1];
    const float* et    = (const float*)d_in[2];
    const float* ot    = (const float*)d_in[3];
    const float* ep    = (const float*)d_in[4];
    const float* op    = (const float*)d_in[5];

    eunn_precompute<<<68, 256>>>(omega, et, ot, ep, op);   // 17408 threads

    // single resident wave: 296 CTAs x 2 g-groups, 7/6 rows per group
    eunn_main<<<296, 256>>>(x, (float*)d_out);
}